// round 7
// baseline (speedup 1.0000x reference)
#include <cuda_runtime.h>
#include <cooperative_groups.h>
namespace cg = cooperative_groups;

#define BB 8
#define CC 64
#define NN 400
#define NN2 (NN * NN)          // 160000
#define NV4 (NN / 4)           // 100
#define TT 16                  // tile dim (400 = 25 * 16, exact)
#define NT 25                  // tiles per dim
#define NPAIR 300              // off-diagonal unordered pairs r<s
#define NDIAGC 13              // diagonal clusters (12 full + 1 half)
#define CLPB (NPAIR + NDIAGC)  // 313 clusters per batch
#define KT 32                  // k-tile width in epilogue

// smem layout (floats)
#define SM_T2   0                          // T2[n][c][k] : 16*64*16 = 16384
#define SM_CM   16384                      // chain maxes: 4*64*4    = 1024
#define SM_APUB (16384 + 1024)             // published A^T          = 256
#define SM_ATP  (16384 + 1024 + 256)       // partner A^T copy       = 256
#define SM_TOTF (16384 + 1024 + 512)       // 17920 floats = 71680 B

// Scratch (device globals: no allocation allowed in kernel_launch)
__device__ float g_xp[NT * BB * CC * NN];  // partial x by source n-tile (20.5 MB)
__device__ float g_x [BB * CC * NN];       // reduced x                  (0.82 MB)

// ---------------------------------------------------------------------------
// Fused single-read kernel. Cluster of 2 CTAs = tile pair (r,s)/(s,r).
// Each CTA: stream its 16x16x64ch tile (65.5 KB) from DRAM with running
// channel-max fused into the load; finalize A^T subtile (relu(tanh(max)));
// exchange A^T with partner via DSMEM; accumulate
//   xp[rt][b][c][k in ct-range] = sum_{n in rt-range} R[b,c,n,k] * A[b,k,n]
// Diagonal tiles are self-paired (no exchange). R is read exactly once.
// ---------------------------------------------------------------------------
__global__ void kfused(const float* __restrict__ R) {
    extern __shared__ float sm[];
    cg::cluster_group cl = cg::this_cluster();
    const int rank  = (int)cl.block_rank();
    const int cid   = (int)blockIdx.x >> 1;
    const int b     = cid / CLPB;
    const int local = cid - b * CLPB;

    int rt, ct;                 // row tile (n-range / output slot), col tile (k-range)
    bool active = true;
    bool have_partner;
    if (local < NPAIR) {
        int r = 0, rem = local;
        while (rem >= (NT - 1) - r) { rem -= (NT - 1) - r; ++r; }
        int s = r + 1 + rem;
        rt = rank ? s : r;
        ct = rank ? r : s;
        have_partner = true;
    } else {
        int d  = local - NPAIR;
        int dg = 2 * d + rank;
        active = (dg < NT);
        rt = ct = active ? dg : 0;
        have_partner = false;   // self-paired
    }

    const int tid   = threadIdx.x;        // 256
    const int p     = tid & 63;           // position: n-row (p>>2), k-quad (p&3)
    const int chain = tid >> 2 >> 4;      // tid>>6 : 4 chains x 16 channels
    const int nl    = p >> 2;
    const int k4    = p & 3;

    // ---- load + running max (16 channels per thread, fused) ----
    if (active) {
        float4 mx = make_float4(-3.4e38f, -3.4e38f, -3.4e38f, -3.4e38f);
        const float* base = R + ((size_t)(b * CC + chain * 16)) * NN2
                              + (size_t)(rt * TT + nl) * NN + ct * TT + k4 * 4;
        #pragma unroll
        for (int ci = 0; ci < 16; ++ci) {
            float4 v = *reinterpret_cast<const float4*>(base + (size_t)ci * NN2);
            int c = chain * 16 + ci;
            *reinterpret_cast<float4*>(sm + SM_T2 + ((nl * CC + c) * TT + k4 * 4)) = v;
            mx.x = fmaxf(mx.x, v.x); mx.y = fmaxf(mx.y, v.y);
            mx.z = fmaxf(mx.z, v.z); mx.w = fmaxf(mx.w, v.w);
        }
        *reinterpret_cast<float4*>(sm + SM_CM + (chain * 64 + p) * 4) = mx;
    }
    __syncthreads();

    // ---- combine 4 chains, relu(tanh), publish A^T: APUB[j=k][i=n] ----
    if (active && tid < 64) {
        float4 m0 = *reinterpret_cast<float4*>(sm + SM_CM + (0 * 64 + tid) * 4);
        float4 m1 = *reinterpret_cast<float4*>(sm + SM_CM + (1 * 64 + tid) * 4);
        float4 m2 = *reinterpret_cast<float4*>(sm + SM_CM + (2 * 64 + tid) * 4);
        float4 m3 = *reinterpret_cast<float4*>(sm + SM_CM + (3 * 64 + tid) * 4);
        float4 m;
        m.x = fmaxf(fmaxf(m0.x, m1.x), fmaxf(m2.x, m3.x));
        m.y = fmaxf(fmaxf(m0.y, m1.y), fmaxf(m2.y, m3.y));
        m.z = fmaxf(fmaxf(m0.z, m1.z), fmaxf(m2.z, m3.z));
        m.w = fmaxf(fmaxf(m0.w, m1.w), fmaxf(m2.w, m3.w));
        int ni = tid >> 2;                 // i = local n row
        int jq = (tid & 3) * 4;            // j = local k quad base
        sm[SM_APUB + (jq + 0) * TT + ni] = (m.x > 0.f) ? tanhf(m.x) : 0.f;
        sm[SM_APUB + (jq + 1) * TT + ni] = (m.y > 0.f) ? tanhf(m.y) : 0.f;
        sm[SM_APUB + (jq + 2) * TT + ni] = (m.z > 0.f) ? tanhf(m.z) : 0.f;
        sm[SM_APUB + (jq + 3) * TT + ni] = (m.w > 0.f) ? tanhf(m.w) : 0.f;
    }

    // ---- sync #1: partner's APUB ready cluster-wide ----
    cl.sync();

    // ---- copy partner's A^T into local buffer (diag: copy own) ----
    if (active) {
        const float* src = sm + SM_APUB;
        if (have_partner)
            src = cl.map_shared_rank(sm + SM_APUB, rank ^ 1);
        sm[SM_ATP + tid] = src[tid];       // 256 floats, 1 per thread
    }

    // ---- sync #2: my copy done, partner may proceed/exit ----
    cl.sync();

    // ---- accumulate: x[b,c,k in ct] += sum_n T2[n][c][k] * ATP[n][k] ----
    if (active) {
        const int c  = tid >> 2;
        const int kg = (tid & 3) * 4;
        float4 acc = make_float4(0.f, 0.f, 0.f, 0.f);
        #pragma unroll
        for (int n = 0; n < TT; ++n) {
            float4 t = *reinterpret_cast<float4*>(sm + SM_T2 + ((n * CC + c) * TT + kg));
            float4 a = *reinterpret_cast<float4*>(sm + SM_ATP + n * TT + kg);
            acc.x = fmaf(t.x, a.x, acc.x);
            acc.y = fmaf(t.y, a.y, acc.y);
            acc.z = fmaf(t.z, a.z, acc.z);
            acc.w = fmaf(t.w, a.w, acc.w);
        }
        *reinterpret_cast<float4*>(
            g_xp + (((size_t)rt * BB + b) * CC + c) * NN + ct * TT + kg) = acc;
    }
}

// ---------------------------------------------------------------------------
// k3a: g_x = sum over 25 n-tile slots of g_xp — flat float4 reduce.
// ---------------------------------------------------------------------------
__global__ void k3a_reduce() {
    const int total4 = BB * CC * NV4;                  // 51200
    int t = blockIdx.x * blockDim.x + threadIdx.x;
    if (t >= total4) return;
    const float4* xp4 = reinterpret_cast<const float4*>(g_xp);
    const int stride4 = BB * CC * NV4;

    float4 s = xp4[t];
    for (int slot = 1; slot < NT; ++slot) {
        float4 v = xp4[(size_t)slot * stride4 + t];
        s.x += v.x; s.y += v.y; s.z += v.z; s.w += v.w;
    }
    reinterpret_cast<float4*>(g_x)[t] = s;
}

// ---------------------------------------------------------------------------
// k3b (R4 verbatim): out[b,o,k] = sum_c W[o,c] * x[b,c,k] + bias[o]
// ---------------------------------------------------------------------------
__global__ void k3b_linear(const float* __restrict__ W,
                           const float* __restrict__ bias,
                           float* __restrict__ out) {
    __shared__ float xs[CC][KT + 1];
    const int b  = blockIdx.z;
    const int og = blockIdx.y;
    const int k0 = blockIdx.x * KT;
    const int x  = threadIdx.x;
    const int y  = threadIdx.y;
    const int k  = k0 + x;
    const bool valid = (k < NN);
    const int kc = valid ? k : (NN - 1);

    for (int c = y; c < CC; c += 8)
        xs[c][x] = g_x[((size_t)b * CC + c) * NN + kc];
    __syncthreads();

    #pragma unroll
    for (int oi = 0; oi < 2; ++oi) {
        int o = og * 16 + y + oi * 8;
        float acc = bias[o];
        const float* wr = W + o * CC;
        #pragma unroll 16
        for (int c = 0; c < CC; ++c)
            acc = fmaf(wr[c], xs[c][x], acc);
        if (valid)
            out[((size_t)b * CC + o) * NN + k] = acc;
    }
}

// ---------------------------------------------------------------------------
extern "C" void kernel_launch(void* const* d_in, const int* in_sizes, int n_in,
                              void* d_out, int out_size) {
    const float* R    = (const float*)d_in[0];
    const float* W    = (const float*)d_in[1];
    const float* bias = (const float*)d_in[2];
    float*       out  = (float*)d_out;

    // Fused single-read kernel: 8 * 313 clusters * 2 CTAs = 5008 blocks
    {
        const size_t smem = SM_TOTF * sizeof(float);   // 71680 B
        cudaFuncSetAttribute(kfused,
                             cudaFuncAttributeMaxDynamicSharedMemorySize,
                             (int)smem);
        cudaLaunchConfig_t cfg = {};
        cfg.gridDim  = dim3(BB * CLPB * 2, 1, 1);
        cfg.blockDim = dim3(256, 1, 1);
        cfg.dynamicSmemBytes = smem;
        cfg.stream = 0;
        cudaLaunchAttribute attrs[1];
        attrs[0].id = cudaLaunchAttributeClusterDimension;
        attrs[0].val.clusterDim = {2, 1, 1};
        cfg.attrs = attrs;
        cfg.numAttrs = 1;
        cudaLaunchKernelEx(&cfg, kfused, R);
    }

    // k3a: 25-slot partial reduce (200 blocks)
    {
        int total4 = BB * CC * NV4;
        k3a_reduce<<<(total4 + 255) / 256, 256>>>();
    }

    // k3b: linear (416 blocks)
    {
        dim3 grid((NN + KT - 1) / KT, 4, BB);
        dim3 blk(32, 8);
        k3b_linear<<<grid, blk>>>(W, bias, out);
    }
}

// round 8
// speedup vs baseline: 1.3180x; 1.3180x over previous
#include <cuda_runtime.h>
#include <cooperative_groups.h>
namespace cg = cooperative_groups;

#define BB 8
#define CC 64
#define NN 400
#define NN2 (NN * NN)          // 160000
#define NV4 (NN / 4)           // 100
#define TT 16                  // tile dim (400 = 25*16 exact)
#define NT 25                  // tiles per dim
#define NPAIR 300              // off-diagonal unordered pairs r<s
#define NDIAGC 13              // diagonal clusters (12 full + 1 half)
#define CLPB (NPAIR + NDIAGC)  // 313 clusters per batch
#define KT 32                  // k-tile width in epilogue

// Scratch (device globals: no allocation allowed in kernel_launch)
__device__ float g_xp[NT * BB * CC * NN];  // partial x by source n-tile (20.5 MB)

// ---------------------------------------------------------------------------
// Fused single-DRAM-read kernel, v2 (no tile staging).
// Cluster of 2 CTAs = tile pair (rt,ct)/(ct,rt). Each CTA:
//   Phase 1: stream its 16x16x64ch tile (65.5 KB) computing channel max only
//            (no smem staging); publish 1KB transposed f-tile APUB[j][i].
//   Exchange APUB with partner via DSMEM (1 KB).
//   Phase 2: RE-READ own tile (L2-hot: this CTA just fetched it) and
//            accumulate xp[rt][b][c][k in ct] = sum_n R[b,c,n,k]*ATP[n][k].
// smem ~6KB -> 6 CTAs/SM (launch_bounds), vs R7's 70KB/3 CTAs.
// ---------------------------------------------------------------------------
__global__ void __launch_bounds__(256, 6) kfused2(const float* __restrict__ R) {
    __shared__ float cm[4 * 64 * 4];      // per-chain maxes (float4 each): 4 KB
    __shared__ float apub[TT * TT];       // my transposed f-tile [j][i]: 1 KB
    __shared__ float atp[TT * TT];        // partner's f-tile copy:       1 KB

    cg::cluster_group cl = cg::this_cluster();
    const int rank  = (int)cl.block_rank();
    const int cid   = (int)blockIdx.x >> 1;
    const int b     = cid / CLPB;
    const int local = cid - b * CLPB;

    int rt, ct;
    bool active = true;
    bool have_partner;
    if (local < NPAIR) {
        int r = 0, rem = local;
        while (rem >= (NT - 1) - r) { rem -= (NT - 1) - r; ++r; }
        int s = r + 1 + rem;
        rt = rank ? s : r;
        ct = rank ? r : s;
        have_partner = true;
    } else {
        int d  = local - NPAIR;
        int dg = 2 * d + rank;
        active = (dg < NT);
        rt = ct = active ? dg : 0;
        have_partner = false;
    }

    const int tid   = threadIdx.x;        // 256
    const int p     = tid & 63;
    const int chain = tid >> 6;           // 0..3 -> channels chain*16..+15
    const int nl    = p >> 2;             // local row 0..15
    const int k4    = p & 3;              // k quad 0..3

    // ---- Phase 1: channel max over my 16 channels at (nl, k4*4..+3) ----
    if (active) {
        const float* base = R + (size_t)(b * CC + chain * 16) * NN2
                              + (size_t)(rt * TT + nl) * NN + ct * TT + k4 * 4;
        float4 mx = *reinterpret_cast<const float4*>(base);
        #pragma unroll
        for (int ci = 1; ci < 16; ++ci) {
            float4 v = *reinterpret_cast<const float4*>(base + (size_t)ci * NN2);
            mx.x = fmaxf(mx.x, v.x); mx.y = fmaxf(mx.y, v.y);
            mx.z = fmaxf(mx.z, v.z); mx.w = fmaxf(mx.w, v.w);
        }
        *reinterpret_cast<float4*>(cm + (chain * 64 + p) * 4) = mx;
    }
    __syncthreads();

    // ---- combine 4 chains, relu(tanh), publish TRANSPOSED: apub[j][i] ----
    if (active && tid < 64) {
        float4 m0 = *reinterpret_cast<float4*>(cm + (0 * 64 + tid) * 4);
        float4 m1 = *reinterpret_cast<float4*>(cm + (1 * 64 + tid) * 4);
        float4 m2 = *reinterpret_cast<float4*>(cm + (2 * 64 + tid) * 4);
        float4 m3 = *reinterpret_cast<float4*>(cm + (3 * 64 + tid) * 4);
        float4 m;
        m.x = fmaxf(fmaxf(m0.x, m1.x), fmaxf(m2.x, m3.x));
        m.y = fmaxf(fmaxf(m0.y, m1.y), fmaxf(m2.y, m3.y));
        m.z = fmaxf(fmaxf(m0.z, m1.z), fmaxf(m2.z, m3.z));
        m.w = fmaxf(fmaxf(m0.w, m1.w), fmaxf(m2.w, m3.w));
        int i  = tid >> 2;                // local row of my tile
        int jq = (tid & 3) * 4;           // local col quad
        apub[(jq + 0) * TT + i] = (m.x > 0.f) ? tanhf(m.x) : 0.f;
        apub[(jq + 1) * TT + i] = (m.y > 0.f) ? tanhf(m.y) : 0.f;
        apub[(jq + 2) * TT + i] = (m.z > 0.f) ? tanhf(m.z) : 0.f;
        apub[(jq + 3) * TT + i] = (m.w > 0.f) ? tanhf(m.w) : 0.f;
    }

    // sync #1: both CTAs' apub ready
    cl.sync();

    // copy partner's apub -> atp (diag: own). 256 floats, 1 per thread.
    if (active) {
        const float* src = apub;
        if (have_partner)
            src = cl.map_shared_rank((const void*)apub, rank ^ 1)
                      ? (const float*)cl.map_shared_rank((void*)apub, rank ^ 1)
                      : apub;
        atp[tid] = src[tid];
    }

    // sync #2: copies complete before anyone may exit
    cl.sync();

    // ---- Phase 2: re-read own tile (L2-hot), accumulate ----
    // atp[n][k_local] = A[b, k, n] for k in ct-range, n in rt-range.
    if (active) {
        const int c  = tid >> 2;          // 0..63
        const int kg = (tid & 3) * 4;     // k quad base
        const float* rb = R + (size_t)(b * CC + c) * NN2
                            + (size_t)(rt * TT) * NN + ct * TT + kg;
        float4 acc = make_float4(0.f, 0.f, 0.f, 0.f);
        #pragma unroll 8
        for (int n = 0; n < TT; ++n) {
            float4 r = *reinterpret_cast<const float4*>(rb + (size_t)n * NN);
            float4 a = *reinterpret_cast<const float4*>(atp + n * TT + kg);
            acc.x = fmaf(r.x, a.x, acc.x);
            acc.y = fmaf(r.y, a.y, acc.y);
            acc.z = fmaf(r.z, a.z, acc.z);
            acc.w = fmaf(r.w, a.w, acc.w);
        }
        *reinterpret_cast<float4*>(
            g_xp + (((size_t)rt * BB + b) * CC + c) * NN + ct * TT + kg) = acc;
    }
}

// ---------------------------------------------------------------------------
// k3f: fused 25-slot reduce + 64x64 linear epilogue.
//   out[b,o,k] = sum_c W[o,c] * (sum_slot xp[slot][b][c][k]) + bias[o]
// 416 blocks; xp reads are L2-hot (20.5 MB just written).
// ---------------------------------------------------------------------------
__global__ void k3f_linear(const float* __restrict__ W,
                           const float* __restrict__ bias,
                           float* __restrict__ out) {
    __shared__ float xs[CC][KT + 1];
    const int b  = blockIdx.z;
    const int og = blockIdx.y;                // 0..3
    const int k0 = blockIdx.x * KT;
    const int x  = threadIdx.x;
    const int y  = threadIdx.y;
    const int k  = k0 + x;
    const bool valid = (k < NN);
    const int kc = valid ? k : (NN - 1);

    for (int c = y; c < CC; c += 8) {
        float s = 0.f;
        #pragma unroll 5
        for (int slot = 0; slot < NT; ++slot)
            s += g_xp[(((size_t)slot * BB + b) * CC + c) * NN + kc];
        xs[c][x] = s;
    }
    __syncthreads();

    #pragma unroll
    for (int oi = 0; oi < 2; ++oi) {
        int o = og * 16 + y + oi * 8;
        float acc = bias[o];
        const float* wr = W + o * CC;
        #pragma unroll 16
        for (int c = 0; c < CC; ++c)
            acc = fmaf(wr[c], xs[c][x], acc);
        if (valid)
            out[((size_t)b * CC + o) * NN + k] = acc;
    }
}

// ---------------------------------------------------------------------------
extern "C" void kernel_launch(void* const* d_in, const int* in_sizes, int n_in,
                              void* d_out, int out_size) {
    const float* R    = (const float*)d_in[0];
    const float* W    = (const float*)d_in[1];
    const float* bias = (const float*)d_in[2];
    float*       out  = (float*)d_out;

    // Fused single-read kernel: 8 * 313 clusters * 2 CTAs = 5008 blocks
    {
        cudaLaunchConfig_t cfg = {};
        cfg.gridDim  = dim3(BB * CLPB * 2, 1, 1);
        cfg.blockDim = dim3(256, 1, 1);
        cfg.dynamicSmemBytes = 0;
        cfg.stream = 0;
        cudaLaunchAttribute attrs[1];
        attrs[0].id = cudaLaunchAttributeClusterDimension;
        attrs[0].val.clusterDim = {2, 1, 1};
        cfg.attrs = attrs;
        cfg.numAttrs = 1;
        cudaLaunchKernelEx(&cfg, kfused2, R);
    }

    // Fused epilogue: 416 blocks
    {
        dim3 grid((NN + KT - 1) / KT, 4, BB);
        dim3 blk(32, 8);
        k3f_linear<<<grid, blk>>>(W, bias, out);
    }
}

// round 9
// speedup vs baseline: 1.4948x; 1.1341x over previous
#include <cuda_runtime.h>
#include <cooperative_groups.h>
namespace cg = cooperative_groups;

#define BB 8
#define CC 64
#define NN 400
#define NN2 (NN * NN)          // 160000
#define NV4 (NN / 4)           // 100
#define TT 16                  // tile dim (400 = 25*16 exact)
#define NT 25                  // tiles per dim
#define NPAIR 300              // off-diagonal unordered pairs r<s
#define NDIAGC 13              // diagonal clusters (12 full + 1 half)
#define CLPB (NPAIR + NDIAGC)  // 313 clusters per batch
#define KT 32                  // k-tile width in epilogue

// Scratch (device globals: no allocation allowed in kernel_launch)
__device__ float g_xp[NT * BB * CC * NN];  // partial x by source n-tile (20.5 MB)
__device__ float g_x [BB * CC * NN];       // reduced x                  (0.82 MB)

// ---------------------------------------------------------------------------
// Fused single-DRAM-read kernel (R8 verbatim — measured ~78us composite).
// Cluster of 2 CTAs = tile pair (rt,ct)/(ct,rt). Phase 1: stream own
// 16x16x64ch tile computing channel max only; publish 1KB transposed f-tile.
// DSMEM exchange. Phase 2: re-read own tile (L2-hot) and accumulate
//   xp[rt][b][c][k in ct] = sum_{n in rt} R[b,c,n,k] * A[b,k,n].
// ---------------------------------------------------------------------------
__global__ void __launch_bounds__(256, 6) kfused2(const float* __restrict__ R) {
    __shared__ float cm[4 * 64 * 4];      // per-chain maxes (float4 each): 4 KB
    __shared__ float apub[TT * TT];       // my transposed f-tile [j][i]: 1 KB
    __shared__ float atp[TT * TT];        // partner's f-tile copy:       1 KB

    cg::cluster_group cl = cg::this_cluster();
    const int rank  = (int)cl.block_rank();
    const int cid   = (int)blockIdx.x >> 1;
    const int b     = cid / CLPB;
    const int local = cid - b * CLPB;

    int rt, ct;
    bool active = true;
    bool have_partner;
    if (local < NPAIR) {
        int r = 0, rem = local;
        while (rem >= (NT - 1) - r) { rem -= (NT - 1) - r; ++r; }
        int s = r + 1 + rem;
        rt = rank ? s : r;
        ct = rank ? r : s;
        have_partner = true;
    } else {
        int d  = local - NPAIR;
        int dg = 2 * d + rank;
        active = (dg < NT);
        rt = ct = active ? dg : 0;
        have_partner = false;
    }

    const int tid   = threadIdx.x;        // 256
    const int p     = tid & 63;
    const int chain = tid >> 6;           // 0..3 -> channels chain*16..+15
    const int nl    = p >> 2;             // local row 0..15
    const int k4    = p & 3;              // k quad 0..3

    // ---- Phase 1: channel max over my 16 channels at (nl, k4*4..+3) ----
    if (active) {
        const float* base = R + (size_t)(b * CC + chain * 16) * NN2
                              + (size_t)(rt * TT + nl) * NN + ct * TT + k4 * 4;
        float4 mx = *reinterpret_cast<const float4*>(base);
        #pragma unroll
        for (int ci = 1; ci < 16; ++ci) {
            float4 v = *reinterpret_cast<const float4*>(base + (size_t)ci * NN2);
            mx.x = fmaxf(mx.x, v.x); mx.y = fmaxf(mx.y, v.y);
            mx.z = fmaxf(mx.z, v.z); mx.w = fmaxf(mx.w, v.w);
        }
        *reinterpret_cast<float4*>(cm + (chain * 64 + p) * 4) = mx;
    }
    __syncthreads();

    // ---- combine 4 chains, relu(tanh), publish TRANSPOSED: apub[j][i] ----
    if (active && tid < 64) {
        float4 m0 = *reinterpret_cast<float4*>(cm + (0 * 64 + tid) * 4);
        float4 m1 = *reinterpret_cast<float4*>(cm + (1 * 64 + tid) * 4);
        float4 m2 = *reinterpret_cast<float4*>(cm + (2 * 64 + tid) * 4);
        float4 m3 = *reinterpret_cast<float4*>(cm + (3 * 64 + tid) * 4);
        float4 m;
        m.x = fmaxf(fmaxf(m0.x, m1.x), fmaxf(m2.x, m3.x));
        m.y = fmaxf(fmaxf(m0.y, m1.y), fmaxf(m2.y, m3.y));
        m.z = fmaxf(fmaxf(m0.z, m1.z), fmaxf(m2.z, m3.z));
        m.w = fmaxf(fmaxf(m0.w, m1.w), fmaxf(m2.w, m3.w));
        int i  = tid >> 2;
        int jq = (tid & 3) * 4;
        apub[(jq + 0) * TT + i] = (m.x > 0.f) ? tanhf(m.x) : 0.f;
        apub[(jq + 1) * TT + i] = (m.y > 0.f) ? tanhf(m.y) : 0.f;
        apub[(jq + 2) * TT + i] = (m.z > 0.f) ? tanhf(m.z) : 0.f;
        apub[(jq + 3) * TT + i] = (m.w > 0.f) ? tanhf(m.w) : 0.f;
    }

    // sync #1: both CTAs' apub ready
    cl.sync();

    // copy partner's apub -> atp (diag: own). 256 floats, 1 per thread.
    if (active) {
        const float* src = apub;
        if (have_partner)
            src = (const float*)cl.map_shared_rank((void*)apub, rank ^ 1);
        atp[tid] = src[tid];
    }

    // sync #2: copies complete before anyone may exit
    cl.sync();

    // ---- Phase 2: re-read own tile (L2-hot), accumulate ----
    if (active) {
        const int c  = tid >> 2;          // 0..63
        const int kg = (tid & 3) * 4;     // k quad base
        const float* rb = R + (size_t)(b * CC + c) * NN2
                            + (size_t)(rt * TT) * NN + ct * TT + kg;
        float4 acc = make_float4(0.f, 0.f, 0.f, 0.f);
        #pragma unroll 8
        for (int n = 0; n < TT; ++n) {
            float4 r = *reinterpret_cast<const float4*>(rb + (size_t)n * NN);
            float4 a = *reinterpret_cast<const float4*>(atp + n * TT + kg);
            acc.x = fmaf(r.x, a.x, acc.x);
            acc.y = fmaf(r.y, a.y, acc.y);
            acc.z = fmaf(r.z, a.z, acc.z);
            acc.w = fmaf(r.w, a.w, acc.w);
        }
        *reinterpret_cast<float4*>(
            g_xp + (((size_t)rt * BB + b) * CC + c) * NN + ct * TT + kg) = acc;
    }
}

// ---------------------------------------------------------------------------
// k3a (R4-proven structure): g_x = sum over 25 slots of g_xp.
// One float4 per thread, 25 independent loads in flight (L2-hot).
// ---------------------------------------------------------------------------
__global__ void k3a_reduce() {
    const int total4 = BB * CC * NV4;                  // 51200
    int t = blockIdx.x * blockDim.x + threadIdx.x;
    if (t >= total4) return;
    const float4* xp4 = reinterpret_cast<const float4*>(g_xp);
    const int stride4 = BB * CC * NV4;

    // 4 independent accumulator chains over the 25 slots
    float4 s0 = xp4[t];
    float4 s1 = xp4[(size_t)1 * stride4 + t];
    float4 s2 = xp4[(size_t)2 * stride4 + t];
    float4 s3 = xp4[(size_t)3 * stride4 + t];
    #pragma unroll
    for (int slot = 4; slot + 3 < NT; slot += 4) {
        float4 v0 = xp4[(size_t)(slot + 0) * stride4 + t];
        float4 v1 = xp4[(size_t)(slot + 1) * stride4 + t];
        float4 v2 = xp4[(size_t)(slot + 2) * stride4 + t];
        float4 v3 = xp4[(size_t)(slot + 3) * stride4 + t];
        s0.x += v0.x; s0.y += v0.y; s0.z += v0.z; s0.w += v0.w;
        s1.x += v1.x; s1.y += v1.y; s1.z += v1.z; s1.w += v1.w;
        s2.x += v2.x; s2.y += v2.y; s2.z += v2.z; s2.w += v2.w;
        s3.x += v3.x; s3.y += v3.y; s3.z += v3.z; s3.w += v3.w;
    }
    // slot 24 tail
    {
        float4 v = xp4[(size_t)24 * stride4 + t];
        s0.x += v.x; s0.y += v.y; s0.z += v.z; s0.w += v.w;
    }
    float4 s;
    s.x = (s0.x + s1.x) + (s2.x + s3.x);
    s.y = (s0.y + s1.y) + (s2.y + s3.y);
    s.z = (s0.z + s1.z) + (s2.z + s3.z);
    s.w = (s0.w + s1.w) + (s2.w + s3.w);
    reinterpret_cast<float4*>(g_x)[t] = s;
}

// ---------------------------------------------------------------------------
// k3b (R4 verbatim): out[b,o,k] = sum_c W[o,c] * x[b,c,k] + bias[o]
// ---------------------------------------------------------------------------
__global__ void k3b_linear(const float* __restrict__ W,
                           const float* __restrict__ bias,
                           float* __restrict__ out) {
    __shared__ float xs[CC][KT + 1];
    const int b  = blockIdx.z;
    const int og = blockIdx.y;
    const int k0 = blockIdx.x * KT;
    const int x  = threadIdx.x;
    const int y  = threadIdx.y;
    const int k  = k0 + x;
    const bool valid = (k < NN);
    const int kc = valid ? k : (NN - 1);

    for (int c = y; c < CC; c += 8)
        xs[c][x] = g_x[((size_t)b * CC + c) * NN + kc];
    __syncthreads();

    #pragma unroll
    for (int oi = 0; oi < 2; ++oi) {
        int o = og * 16 + y + oi * 8;
        float acc = bias[o];
        const float* wr = W + o * CC;
        #pragma unroll 16
        for (int c = 0; c < CC; ++c)
            acc = fmaf(wr[c], xs[c][x], acc);
        if (valid)
            out[((size_t)b * CC + o) * NN + k] = acc;
    }
}

// ---------------------------------------------------------------------------
extern "C" void kernel_launch(void* const* d_in, const int* in_sizes, int n_in,
                              void* d_out, int out_size) {
    const float* R    = (const float*)d_in[0];
    const float* W    = (const float*)d_in[1];
    const float* bias = (const float*)d_in[2];
    float*       out  = (float*)d_out;

    // Fused single-read kernel: 8 * 313 clusters * 2 CTAs = 5008 blocks
    {
        cudaLaunchConfig_t cfg = {};
        cfg.gridDim  = dim3(BB * CLPB * 2, 1, 1);
        cfg.blockDim = dim3(256, 1, 1);
        cfg.dynamicSmemBytes = 0;
        cfg.stream = 0;
        cudaLaunchAttribute attrs[1];
        attrs[0].id = cudaLaunchAttributeClusterDimension;
        attrs[0].val.clusterDim = {2, 1, 1};
        cfg.attrs = attrs;
        cfg.numAttrs = 1;
        cudaLaunchKernelEx(&cfg, kfused2, R);
    }

    // k3a: 25-slot partial reduce (200 blocks)
    {
        int total4 = BB * CC * NV4;
        k3a_reduce<<<(total4 + 255) / 256, 256>>>();
    }

    // k3b: linear (416 blocks)
    {
        dim3 grid((NN + KT - 1) / KT, 4, BB);
        dim3 blk(32, 8);
        k3b_linear<<<grid, blk>>>(W, bias, out);
    }
}